// round 13
// baseline (speedup 1.0000x reference)
#include <cuda_runtime.h>
#include <cuda_fp16.h>

// ---------------- scratch (device globals; no allocation allowed) ----------
#define NMAX  100032
#define ECAP  1664000

__device__ __half g_h [NMAX * 64];   // GEMM output (pre-scaled by dis[row]), fp16
__device__ __half g_a [NMAX * 64];   // post-aggregation activations, fp16
__device__ float  g_dis[NMAX];
__device__ int    g_cnt[NMAX];       // zero at entry (module init / scan1 re-zero)
__device__ int    g_rptr[NMAX];      // after fill: block-local inclusive prefix
__device__ int    g_col[ECAP];
__device__ int    g_bsum[128];       // exclusive scan of block totals (carry)

// ---------------- preprocessing kernels ------------------------------------

__global__ void k_hist(const int* __restrict__ dst, int E) {
    int e = (blockIdx.x * 256 + threadIdx.x) * 4;
    if (e + 4 <= E) {
        int4 d = *(const int4*)(dst + e);
        atomicAdd(&g_cnt[d.x], 1);
        atomicAdd(&g_cnt[d.y], 1);
        atomicAdd(&g_cnt[d.z], 1);
        atomicAdd(&g_cnt[d.w], 1);
    } else {
        for (; e < E; e++) atomicAdd(&g_cnt[dst[e]], 1);
    }
}

// block-wide exclusive scan helper (blockDim.x == 1024)
__device__ __forceinline__ int blockscan_excl(int v, int* total) {
    __shared__ int ws[32];
    int lane = threadIdx.x & 31, wid = threadIdx.x >> 5;
    int s = v;
#pragma unroll
    for (int o = 1; o < 32; o <<= 1) {
        int t = __shfl_up_sync(0xffffffffu, s, o);
        if (lane >= o) s += t;
    }
    if (lane == 31) ws[wid] = s;
    __syncthreads();
    if (wid == 0) {
        int u = ws[lane];
#pragma unroll
        for (int o = 1; o < 32; o <<= 1) {
            int t = __shfl_up_sync(0xffffffffu, u, o);
            if (lane >= o) u += t;
        }
        ws[lane] = u;
    }
    __syncthreads();
    int incl = s + (wid ? ws[wid - 1] : 0);
    if (total) *total = ws[31];
    return incl - v;
}

// per-block exclusive scan of cnt -> rptr (local), block totals -> bsum,
// fused with dis = rsqrt(deg+1). Also re-zeroes g_cnt so the next graph
// replay's hist starts from zero (module load zero-inits for call #1).
__global__ void k_scan1(int n) {
    int i = blockIdx.x * 1024 + threadIdx.x;
    int v = (i < n) ? g_cnt[i] : 0;
    int tot;
    int ex = blockscan_excl(v, &tot);
    if (i < n) {
        g_rptr[i] = ex;
        g_dis[i] = rsqrtf((float)(v + 1));   // +1 self loop; always > 0
        g_cnt[i] = 0;
    }
    if (threadIdx.x == 0) g_bsum[blockIdx.x] = tot;
}

// exclusive scan of block sums (single block)
__global__ void k_scan2(int nb) {
    int i = threadIdx.x;
    int v = (i < nb) ? g_bsum[i] : 0;   // reads complete before writes (barrier in scan)
    int ex = blockscan_excl(v, nullptr);
    if (i < nb) g_bsum[i] = ex;
}

// ---------------- mma.sync helpers ------------------------------------------
__device__ __forceinline__ void mma16816(float acc[4], const unsigned a[4],
                                         const unsigned b[2]) {
    asm volatile(
        "mma.sync.aligned.m16n8k16.row.col.f32.f16.f16.f32 "
        "{%0,%1,%2,%3}, {%4,%5,%6,%7}, {%8,%9}, {%0,%1,%2,%3};\n"
        : "+f"(acc[0]), "+f"(acc[1]), "+f"(acc[2]), "+f"(acc[3])
        : "r"(a[0]), "r"(a[1]), "r"(a[2]), "r"(a[3]), "r"(b[0]), "r"(b[1]));
}

__device__ __forceinline__ unsigned pack_hi(float2 f, unsigned& lo) {
    __half hx = __float2half_rn(f.x), hy = __float2half_rn(f.y);
    __half2 l2 = __halves2half2(__float2half_rn(f.x - __half2float(hx)),
                                __float2half_rn(f.y - __half2float(hy)));
    lo = *(unsigned*)&l2;
    __half2 h2 = __halves2half2(hx, hy);
    return *(unsigned*)&h2;
}

// Stage W[K][64] (row-major fp32) into per-thread B-fragment records:
//   sB[(ks*64 + nn)*4 + t] = {bh0, bh1, bl0, bl1}; decomposition of i must
//   match consumer index: t = i&3, nn = (i>>2)&63, ks = i>>8.
template <int K>
__device__ __forceinline__ void stage_B(uint4* sB, const float* __restrict__ W,
                                        int tid) {
    constexpr int ENT = (K / 16) * 64 * 4;
    for (int i = tid; i < ENT; i += 256) {
        int t = i & 3;
        int nn = (i >> 2) & 63;
        int ks = i >> 8;
        int k0 = ks * 16 + t * 2;
        float w0 = W[k0 * 64 + nn],       w1 = W[(k0 + 1) * 64 + nn];
        float w2 = W[(k0 + 8) * 64 + nn], w3 = W[(k0 + 9) * 64 + nn];
        unsigned l01, l23;
        uint4 v;
        v.x = pack_hi(make_float2(w0, w1), l01);
        v.y = pack_hi(make_float2(w2, w3), l23);
        v.z = l01;
        v.w = l23;
        sB[i] = v;
    }
}

// ---------------- FUSED: gemm1 + CSR fill, role-interleaved ------------------
// Roles alternate with blockIdx over the paired prefix so every scheduling
// wave holds both kinds. __launch_bounds__(256, 6) caps regs (~42) so 6
// blocks/SM co-reside (~3 gemm + 3 fill): the prior regs=54 build got only
// 4/SM, halving gemm's resident issue width and stretching the kernel to
// ~serial. A-staging transients may spill to local (L1); acc stays in regs.
__global__ void __launch_bounds__(256, 6) k_gemm1_fill(
        const float* __restrict__ Ain, const float* __restrict__ W, int n, int gb,
        const int* __restrict__ src, const int* __restrict__ dst, int E, int e4b) {
    constexpr int K = 128;
    extern __shared__ __align__(16) uint4 sB[];   // [(K/16)*64*4] = 32 KB

    int mn = (gb < e4b) ? gb : e4b;
    int m2 = 2 * mn;
    bool isFill;
    int id;
    if ((int)blockIdx.x < m2) {
        isFill = (blockIdx.x & 1) == 0;
        id = blockIdx.x >> 1;
    } else {
        int rem = blockIdx.x - m2;
        isFill = (e4b > gb);
        id = mn + rem;
    }

    if (isFill) {
        // ---------------- fill body ----------------
        int e = (id * 256 + threadIdx.x) * 4;
        if (e + 4 <= E) {
            int4 d = *(const int4*)(dst + e);
            int4 s = *(const int4*)(src + e);
            g_col[atomicAdd(&g_rptr[d.x], 1) + g_bsum[d.x >> 10]] = s.x;
            g_col[atomicAdd(&g_rptr[d.y], 1) + g_bsum[d.y >> 10]] = s.y;
            g_col[atomicAdd(&g_rptr[d.z], 1) + g_bsum[d.z >> 10]] = s.z;
            g_col[atomicAdd(&g_rptr[d.w], 1) + g_bsum[d.w >> 10]] = s.w;
        } else {
            for (; e < E; e++) {
                int d = dst[e];
                g_col[atomicAdd(&g_rptr[d], 1) + g_bsum[d >> 10]] = src[e];
            }
        }
        return;
    }

    // ---------------- gemm1 body ----------------
    int tid = threadIdx.x;
    int wid = tid >> 5, lane = tid & 31;
    int wm = wid & 3, wn = wid >> 2;
    int row0 = id * 64;

    stage_B<K>(sB, W, tid);
    __syncthreads();

    float acc[4][4];
#pragma unroll
    for (int f = 0; f < 4; f++)
#pragma unroll
        for (int j = 0; j < 4; j++) acc[f][j] = 0.f;

    int g = lane >> 2, t = lane & 3;
    int r0 = row0 + wm * 16 + g, r1 = r0 + 8;
    bool ok0 = r0 < n, ok1 = r1 < n;
    const float* A0 = Ain + (size_t)r0 * K;
    const float* A1 = Ain + (size_t)r1 * K;
    const float2 z2 = make_float2(0.f, 0.f);

#pragma unroll
    for (int ks = 0; ks < K / 16; ks++) {
        int kk = ks * 16 + t * 2;
        float2 f0 = ok0 ? *(const float2*)(A0 + kk) : z2;
        float2 f1 = ok1 ? *(const float2*)(A1 + kk) : z2;
        float2 f2 = ok0 ? *(const float2*)(A0 + kk + 8) : z2;
        float2 f3 = ok1 ? *(const float2*)(A1 + kk + 8) : z2;
        unsigned ah[4], al[4];
        ah[0] = pack_hi(f0, al[0]);
        ah[1] = pack_hi(f1, al[1]);
        ah[2] = pack_hi(f2, al[2]);
        ah[3] = pack_hi(f3, al[3]);
#pragma unroll
        for (int nf = 0; nf < 4; nf++) {
            int nn = wn * 32 + nf * 8 + g;
            uint4 v = sB[(ks * 64 + nn) * 4 + t];
            unsigned bh[2] = {v.x, v.y}, bl[2] = {v.z, v.w};
            mma16816(acc[nf], ah, bh);
            mma16816(acc[nf], ah, bl);
            mma16816(acc[nf], al, bh);
        }
    }

    float d0 = ok0 ? g_dis[r0] : 0.f;
    float d1 = ok1 ? g_dis[r1] : 0.f;
#pragma unroll
    for (int nf = 0; nf < 4; nf++) {
        int col = wn * 32 + nf * 8 + t * 2;
        if (ok0)
            *(__half2*)(g_h + (size_t)r0 * 64 + col) =
                __floats2half2_rn(acc[nf][0] * d0, acc[nf][1] * d0);
        if (ok1)
            *(__half2*)(g_h + (size_t)r1 * 64 + col) =
                __floats2half2_rn(acc[nf][2] * d1, acc[nf][3] * d1);
    }
}

// ---------------- GEMM2 via mma.sync ----------------------------------------
// H[n,64] = (g_a[n,64] @ W2) * dis[row] -> fp16 g_h ; A exact fp16 from smem.
__global__ void __launch_bounds__(256) k_gemm2_mma(const float* __restrict__ W, int n) {
    constexpr int K = 64;
    constexpr int LD = K + 8;
    extern __shared__ __align__(16) uint4 dynu[];
    uint4* sB = dynu;                                   // [(K/16)*64*4] = 16 KB
    __half* sAh = (__half*)(dynu + (K / 16) * 64 * 4);  // [64][LD]

    int tid = threadIdx.x;
    int wid = tid >> 5, lane = tid & 31;
    int wm = wid & 3, wn = wid >> 2;
    int row0 = blockIdx.x * 64;

    stage_B<K>(sB, W, tid);
    for (int i = tid; i < 64 * (K / 8); i += 256) {
        int row = i / (K / 8), c8 = i % (K / 8);
        uint4 v = *(const uint4*)(g_a + (size_t)(row0 + row) * K + c8 * 8);
        *(uint4*)(sAh + row * LD + c8 * 8) = v;
    }
    __syncthreads();

    float acc[4][4];
#pragma unroll
    for (int f = 0; f < 4; f++)
#pragma unroll
        for (int j = 0; j < 4; j++) acc[f][j] = 0.f;

    int g = lane >> 2, t = lane & 3;

#pragma unroll
    for (int ks = 0; ks < K / 16; ks++) {
        int kk = ks * 16 + t * 2;
        int r = wm * 16 + g;
        unsigned ah[4];
        ah[0] = *(const unsigned*)(sAh + r * LD + kk);
        ah[1] = *(const unsigned*)(sAh + (r + 8) * LD + kk);
        ah[2] = *(const unsigned*)(sAh + r * LD + kk + 8);
        ah[3] = *(const unsigned*)(sAh + (r + 8) * LD + kk + 8);
#pragma unroll
        for (int nf = 0; nf < 4; nf++) {
            int nn = wn * 32 + nf * 8 + g;
            uint4 v = sB[(ks * 64 + nn) * 4 + t];
            unsigned bh[2] = {v.x, v.y}, bl[2] = {v.z, v.w};
            mma16816(acc[nf], ah, bh);
            mma16816(acc[nf], ah, bl);
        }
    }

    int r0 = row0 + wm * 16 + g, r1 = r0 + 8;
    float d0 = (r0 < n) ? g_dis[r0] : 0.f;
    float d1 = (r1 < n) ? g_dis[r1] : 0.f;
#pragma unroll
    for (int nf = 0; nf < 4; nf++) {
        int col = wn * 32 + nf * 8 + t * 2;
        if (r0 < n)
            *(__half2*)(g_h + (size_t)r0 * 64 + col) =
                __floats2half2_rn(acc[nf][0] * d0, acc[nf][1] * d0);
        if (r1 < n)
            *(__half2*)(g_h + (size_t)r1 * 64 + col) =
                __floats2half2_rn(acc[nf][2] * d1, acc[nf][3] * d1);
    }
}

// ---------------- aggregation: warp per dst node (R10 proven body) ----------
template <bool FC>
__global__ void __launch_bounds__(256) k_agg(const float* __restrict__ bias,
                                             const float* __restrict__ Wfc,
                                             const float* __restrict__ bfc,
                                             float* __restrict__ out, int n) {
    int w = (blockIdx.x * 256 + threadIdx.x) >> 5;
    int lane = threadIdx.x & 31;
    if (w >= n) return;

    int start = w ? (__ldg(&g_rptr[w - 1]) + __ldg(&g_bsum[(w - 1) >> 10])) : 0;
    int end = __ldg(&g_rptr[w]) + __ldg(&g_bsum[w >> 10]);

    const __half2* __restrict__ H2 = (const __half2*)g_h;
    float2 acc = __half22float2(H2[(size_t)w * 32 + lane]);   // self loop

    int e = start;
    for (; e + 4 <= end; e += 4) {
        int s0 = __ldg(&g_col[e]), s1 = __ldg(&g_col[e + 1]);
        int s2 = __ldg(&g_col[e + 2]), s3 = __ldg(&g_col[e + 3]);
        float2 v0 = __half22float2(H2[(size_t)s0 * 32 + lane]);
        float2 v1 = __half22float2(H2[(size_t)s1 * 32 + lane]);
        float2 v2 = __half22float2(H2[(size_t)s2 * 32 + lane]);
        float2 v3 = __half22float2(H2[(size_t)s3 * 32 + lane]);
        acc.x += (v0.x + v1.x) + (v2.x + v3.x);
        acc.y += (v0.y + v1.y) + (v2.y + v3.y);
    }
    for (; e < end; e++) {
        float2 v = __half22float2(H2[(size_t)__ldg(&g_col[e]) * 32 + lane]);
        acc.x += v.x;
        acc.y += v.y;
    }

    float d = g_dis[w];
    float2 b = ((const float2*)bias)[lane];
    float ox = fmaxf(fmaf(acc.x, d, b.x), 0.f);
    float oy = fmaxf(fmaf(acc.y, d, b.y), 0.f);

    if (!FC) {
        ((__half2*)g_a)[(size_t)w * 32 + lane] = __floats2half2_rn(ox, oy);
    } else {
        const float4* Wf = (const float4*)Wfc;   // [64][4]
        float4 w0 = Wf[2 * lane], w1 = Wf[2 * lane + 1];
        float4 y;
        y.x = ox * w0.x + oy * w1.x;
        y.y = ox * w0.y + oy * w1.y;
        y.z = ox * w0.z + oy * w1.z;
        y.w = ox * w0.w + oy * w1.w;
#pragma unroll
        for (int o = 16; o; o >>= 1) {
            y.x += __shfl_xor_sync(0xffffffffu, y.x, o);
            y.y += __shfl_xor_sync(0xffffffffu, y.y, o);
            y.z += __shfl_xor_sync(0xffffffffu, y.z, o);
            y.w += __shfl_xor_sync(0xffffffffu, y.w, o);
        }
        if (lane == 0) {
            float4 bf = *(const float4*)bfc;
            ((float4*)out)[w] = make_float4(y.x + bf.x, y.y + bf.y, y.z + bf.z, y.w + bf.w);
        }
    }
}

// ---------------- launch ----------------------------------------------------

extern "C" void kernel_launch(void* const* d_in, const int* in_sizes, int n_in,
                              void* d_out, int out_size) {
    const float* x   = (const float*)d_in[0];
    const int*   ei  = (const int*)d_in[1];
    const float* W1  = (const float*)d_in[2];
    const float* b1  = (const float*)d_in[3];
    const float* W2  = (const float*)d_in[4];
    const float* b2  = (const float*)d_in[5];
    const float* Wfc = (const float*)d_in[6];
    const float* bfc = (const float*)d_in[7];

    int n = in_sizes[0] / 128;
    int E = in_sizes[1] / 2;
    if (n > NMAX) n = NMAX;
    if (E > ECAP) E = ECAP;
    const int* src = ei;
    const int* dst = ei + E;
    int nb = (n + 1023) / 1024;
    int e4b = (E / 4 + 256) / 256;
    int gb = (n + 63) / 64;

    const int SMF = (128 / 16) * 64 * 4 * 16;                    // 32768
    const int SM2 = (64 / 16) * 64 * 4 * 16 + 64 * (64 + 8) * 2; // 25600
    cudaFuncSetAttribute(k_gemm1_fill,
                         cudaFuncAttributeMaxDynamicSharedMemorySize, SMF);
    cudaFuncSetAttribute(k_gemm2_mma,
                         cudaFuncAttributeMaxDynamicSharedMemorySize, SM2);

    k_hist<<<e4b, 256>>>(dst, E);
    k_scan1<<<nb, 1024>>>(n);
    k_scan2<<<1, 1024>>>(nb);

    // fused: gemm1 + CSR fill, roles interleaved across the grid
    k_gemm1_fill<<<gb + e4b, 256, SMF>>>(x, W1, n, gb, src, dst, E, e4b);

    k_agg<false><<<(n + 7) / 8, 256>>>(b1, nullptr, nullptr, nullptr, n);
    k_gemm2_mma<<<gb, 256, SM2>>>(W2, n);
    k_agg<true><<<(n + 7) / 8, 256>>>(b2, Wfc, bfc, (float*)d_out, n);
}

// round 14
// speedup vs baseline: 1.0291x; 1.0291x over previous
#include <cuda_runtime.h>
#include <cuda_fp16.h>

// ---------------- scratch (device globals; no allocation allowed) ----------
#define NMAX  100032
#define ECAP  1664000

__device__ __half g_h [NMAX * 64];   // GEMM output (pre-scaled by dis[row]), fp16
__device__ __half g_a [NMAX * 64];   // post-aggregation activations, fp16
__device__ float  g_dis[NMAX];
__device__ int    g_cnt[NMAX];       // zero at entry (module init / scan1 re-zero)
__device__ int    g_rptr[NMAX];      // after fill: block-local inclusive prefix
__device__ int    g_col[ECAP];
__device__ int    g_bsum[128];       // exclusive scan of block totals (carry)

// ---------------- preprocessing kernels ------------------------------------

__global__ void k_hist(const int* __restrict__ dst, int E) {
    int e = (blockIdx.x * 256 + threadIdx.x) * 4;
    if (e + 4 <= E) {
        int4 d = *(const int4*)(dst + e);
        atomicAdd(&g_cnt[d.x], 1);
        atomicAdd(&g_cnt[d.y], 1);
        atomicAdd(&g_cnt[d.z], 1);
        atomicAdd(&g_cnt[d.w], 1);
    } else {
        for (; e < E; e++) atomicAdd(&g_cnt[dst[e]], 1);
    }
}

// block-wide exclusive scan helper (blockDim.x == 1024)
__device__ __forceinline__ int blockscan_excl(int v, int* total) {
    __shared__ int ws[32];
    int lane = threadIdx.x & 31, wid = threadIdx.x >> 5;
    int s = v;
#pragma unroll
    for (int o = 1; o < 32; o <<= 1) {
        int t = __shfl_up_sync(0xffffffffu, s, o);
        if (lane >= o) s += t;
    }
    if (lane == 31) ws[wid] = s;
    __syncthreads();
    if (wid == 0) {
        int u = ws[lane];
#pragma unroll
        for (int o = 1; o < 32; o <<= 1) {
            int t = __shfl_up_sync(0xffffffffu, u, o);
            if (lane >= o) u += t;
        }
        ws[lane] = u;
    }
    __syncthreads();
    int incl = s + (wid ? ws[wid - 1] : 0);
    if (total) *total = ws[31];
    return incl - v;
}

// per-block exclusive scan of cnt -> rptr (local), block totals -> bsum,
// fused with dis = rsqrt(deg+1). Re-zeroes g_cnt so the next graph replay's
// hist starts from zero (module load zero-inits for call #1). Proven in R13.
__global__ void k_scan1(int n) {
    int i = blockIdx.x * 1024 + threadIdx.x;
    int v = (i < n) ? g_cnt[i] : 0;
    int tot;
    int ex = blockscan_excl(v, &tot);
    if (i < n) {
        g_rptr[i] = ex;
        g_dis[i] = rsqrtf((float)(v + 1));   // +1 self loop; always > 0
        g_cnt[i] = 0;
    }
    if (threadIdx.x == 0) g_bsum[blockIdx.x] = tot;
}

// exclusive scan of block sums (single block)
__global__ void k_scan2(int nb) {
    int i = threadIdx.x;
    int v = (i < nb) ? g_bsum[i] : 0;   // reads complete before writes (barrier in scan)
    int ex = blockscan_excl(v, nullptr);
    if (i < nb) g_bsum[i] = ex;
}

// ---------------- mma.sync helpers ------------------------------------------
__device__ __forceinline__ void mma16816(float acc[4], const unsigned a[4],
                                         const unsigned b[2]) {
    asm volatile(
        "mma.sync.aligned.m16n8k16.row.col.f32.f16.f16.f32 "
        "{%0,%1,%2,%3}, {%4,%5,%6,%7}, {%8,%9}, {%0,%1,%2,%3};\n"
        : "+f"(acc[0]), "+f"(acc[1]), "+f"(acc[2]), "+f"(acc[3])
        : "r"(a[0]), "r"(a[1]), "r"(a[2]), "r"(a[3]), "r"(b[0]), "r"(b[1]));
}

__device__ __forceinline__ unsigned pack_hi(float2 f, unsigned& lo) {
    __half hx = __float2half_rn(f.x), hy = __float2half_rn(f.y);
    __half2 l2 = __halves2half2(__float2half_rn(f.x - __half2float(hx)),
                                __float2half_rn(f.y - __half2float(hy)));
    lo = *(unsigned*)&l2;
    __half2 h2 = __halves2half2(hx, hy);
    return *(unsigned*)&h2;
}

// Stage W[K][64] (row-major fp32) into per-thread B-fragment records:
//   sB[(ks*64 + nn)*4 + t] = {bh0, bh1, bl0, bl1}; decomposition of i must
//   match consumer index: t = i&3, nn = (i>>2)&63, ks = i>>8.
template <int K>
__device__ __forceinline__ void stage_B(uint4* sB, const float* __restrict__ W,
                                        int tid) {
    constexpr int ENT = (K / 16) * 64 * 4;
    for (int i = tid; i < ENT; i += 256) {
        int t = i & 3;
        int nn = (i >> 2) & 63;
        int ks = i >> 8;
        int k0 = ks * 16 + t * 2;
        float w0 = W[k0 * 64 + nn],       w1 = W[(k0 + 1) * 64 + nn];
        float w2 = W[(k0 + 8) * 64 + nn], w3 = W[(k0 + 9) * 64 + nn];
        unsigned l01, l23;
        uint4 v;
        v.x = pack_hi(make_float2(w0, w1), l01);
        v.y = pack_hi(make_float2(w2, w3), l23);
        v.z = l01;
        v.w = l23;
        sB[i] = v;
    }
}

// ---------------- FUSED: gemm1 + CSR fill, role-interleaved ------------------
// gemm1 body = R6-proven smem-staged form: A tile converted ONCE to hi/lo fp16
// planes via fully-coalesced float4 loads; W^T staged hi/lo; mainloop fragments
// come from conflict-free LDS (LD=136 -> bank = 4g+t, all 32 lanes distinct).
// This minimizes L1tex wavefronts, freeing the LSU for fill's atomics.
// fill body unchanged. 1:1 role interleave across the paired prefix.
__global__ void __launch_bounds__(256) k_gemm1_fill(
        const float* __restrict__ Ain, const float* __restrict__ W, int n, int gb,
        const int* __restrict__ src, const int* __restrict__ dst, int E, int e4b) {
    constexpr int K = 128;
    constexpr int LD = K + 8;                    // halves per row
    extern __shared__ __align__(16) char dyn[];  // 4 planes x 64*LD halves = 69632 B

    int mn = (gb < e4b) ? gb : e4b;
    int m2 = 2 * mn;
    bool isFill;
    int id;
    if ((int)blockIdx.x < m2) {
        isFill = (blockIdx.x & 1) == 0;
        id = blockIdx.x >> 1;
    } else {
        int rem = blockIdx.x - m2;
        isFill = (e4b > gb);
        id = mn + rem;
    }

    if (isFill) {
        // ---------------- fill body ----------------
        int e = (id * 256 + threadIdx.x) * 4;
        if (e + 4 <= E) {
            int4 d = *(const int4*)(dst + e);
            int4 s = *(const int4*)(src + e);
            g_col[atomicAdd(&g_rptr[d.x], 1) + g_bsum[d.x >> 10]] = s.x;
            g_col[atomicAdd(&g_rptr[d.y], 1) + g_bsum[d.y >> 10]] = s.y;
            g_col[atomicAdd(&g_rptr[d.z], 1) + g_bsum[d.z >> 10]] = s.z;
            g_col[atomicAdd(&g_rptr[d.w], 1) + g_bsum[d.w >> 10]] = s.w;
        } else {
            for (; e < E; e++) {
                int d = dst[e];
                g_col[atomicAdd(&g_rptr[d], 1) + g_bsum[d >> 10]] = src[e];
            }
        }
        return;
    }

    // ---------------- gemm1 body (R6-proven) ----------------
    __half* sWh = (__half*)dyn;              // [64][LD]  W^T hi
    __half* sWl = sWh + 64 * LD;             // [64][LD]  W^T lo
    __half* sAh = sWl + 64 * LD;             // [64][LD]  A hi
    __half* sAl = sAh + 64 * LD;             // [64][LD]  A lo

    int tid = threadIdx.x;
    int wid = tid >> 5, lane = tid & 31;
    int wm = wid & 3, wn = wid >> 2;
    int row0 = id * 64;

    // stage W transposed, hi/lo split
    for (int i = tid; i < K * 64; i += 256) {
        int k = i >> 6, nn = i & 63;
        float w = W[i];
        __half h = __float2half_rn(w);
        sWh[nn * LD + k] = h;
        sWl[nn * LD + k] = __float2half_rn(w - __half2float(h));
    }

    // stage A hi/lo (coalesced float4 loads; each element read once)
    for (int i = tid; i < 64 * (K / 4); i += 256) {
        int row = i / (K / 4), c4 = i % (K / 4);
        int grow = row0 + row;
        float4 v = (grow < n) ? *(const float4*)(Ain + (size_t)grow * K + c4 * 4)
                              : make_float4(0.f, 0.f, 0.f, 0.f);
        __half hx = __float2half_rn(v.x), hy = __float2half_rn(v.y);
        __half hz = __float2half_rn(v.z), hw = __float2half_rn(v.w);
        __half* ph = sAh + row * LD + c4 * 4;
        ph[0] = hx; ph[1] = hy; ph[2] = hz; ph[3] = hw;
        __half* pl = sAl + row * LD + c4 * 4;
        pl[0] = __float2half_rn(v.x - __half2float(hx));
        pl[1] = __float2half_rn(v.y - __half2float(hy));
        pl[2] = __float2half_rn(v.z - __half2float(hz));
        pl[3] = __float2half_rn(v.w - __half2float(hw));
    }
    __syncthreads();

    float acc[4][4];
#pragma unroll
    for (int f = 0; f < 4; f++)
#pragma unroll
        for (int j = 0; j < 4; j++) acc[f][j] = 0.f;

    int g = lane >> 2, t = lane & 3;

#pragma unroll
    for (int ks = 0; ks < K / 16; ks++) {
        int kk = ks * 16 + t * 2;
        int r = wm * 16 + g;
        unsigned ah[4], al[4];
        ah[0] = *(const unsigned*)(sAh + r * LD + kk);
        ah[1] = *(const unsigned*)(sAh + (r + 8) * LD + kk);
        ah[2] = *(const unsigned*)(sAh + r * LD + kk + 8);
        ah[3] = *(const unsigned*)(sAh + (r + 8) * LD + kk + 8);
        al[0] = *(const unsigned*)(sAl + r * LD + kk);
        al[1] = *(const unsigned*)(sAl + (r + 8) * LD + kk);
        al[2] = *(const unsigned*)(sAl + r * LD + kk + 8);
        al[3] = *(const unsigned*)(sAl + (r + 8) * LD + kk + 8);
#pragma unroll
        for (int nf = 0; nf < 4; nf++) {
            int nn = wn * 32 + nf * 8 + g;
            unsigned bh[2], bl[2];
            bh[0] = *(const unsigned*)(sWh + nn * LD + kk);
            bh[1] = *(const unsigned*)(sWh + nn * LD + kk + 8);
            bl[0] = *(const unsigned*)(sWl + nn * LD + kk);
            bl[1] = *(const unsigned*)(sWl + nn * LD + kk + 8);
            mma16816(acc[nf], ah, bh);
            mma16816(acc[nf], ah, bl);
            mma16816(acc[nf], al, bh);
        }
    }

    // epilogue: scale by dis[row], store fp16
    int r0 = row0 + wm * 16 + g, r1 = r0 + 8;
    float d0 = (r0 < n) ? g_dis[r0] : 0.f;
    float d1 = (r1 < n) ? g_dis[r1] : 0.f;
#pragma unroll
    for (int nf = 0; nf < 4; nf++) {
        int col = wn * 32 + nf * 8 + t * 2;
        if (r0 < n)
            *(__half2*)(g_h + (size_t)r0 * 64 + col) =
                __floats2half2_rn(acc[nf][0] * d0, acc[nf][1] * d0);
        if (r1 < n)
            *(__half2*)(g_h + (size_t)r1 * 64 + col) =
                __floats2half2_rn(acc[nf][2] * d1, acc[nf][3] * d1);
    }
}

// ---------------- GEMM2 via mma.sync (R10 proven) ---------------------------
// H[n,64] = (g_a[n,64] @ W2) * dis[row] -> fp16 g_h ; A exact fp16 from smem.
__global__ void __launch_bounds__(256) k_gemm2_mma(const float* __restrict__ W, int n) {
    constexpr int K = 64;
    constexpr int LD = K + 8;
    extern __shared__ __align__(16) uint4 dynu[];
    uint4* sB = dynu;                                   // [(K/16)*64*4] = 16 KB
    __half* sAh = (__half*)(dynu + (K / 16) * 64 * 4);  // [64][LD]

    int tid = threadIdx.x;
    int wid = tid >> 5, lane = tid & 31;
    int wm = wid & 3, wn = wid >> 2;
    int row0 = blockIdx.x * 64;

    stage_B<K>(sB, W, tid);
    for (int i = tid; i < 64 * (K / 8); i += 256) {
        int row = i / (K / 8), c8 = i % (K / 8);
        uint4 v = *(const uint4*)(g_a + (size_t)(row0 + row) * K + c8 * 8);
        *(uint4*)(sAh + row * LD + c8 * 8) = v;
    }
    __syncthreads();

    float acc[4][4];
#pragma unroll
    for (int f = 0; f < 4; f++)
#pragma unroll
        for (int j = 0; j < 4; j++) acc[f][j] = 0.f;

    int g = lane >> 2, t = lane & 3;

#pragma unroll
    for (int ks = 0; ks < K / 16; ks++) {
        int kk = ks * 16 + t * 2;
        int r = wm * 16 + g;
        unsigned ah[4];
        ah[0] = *(const unsigned*)(sAh + r * LD + kk);
        ah[1] = *(const unsigned*)(sAh + (r + 8) * LD + kk);
        ah[2] = *(const unsigned*)(sAh + r * LD + kk + 8);
        ah[3] = *(const unsigned*)(sAh + (r + 8) * LD + kk + 8);
#pragma unroll
        for (int nf = 0; nf < 4; nf++) {
            int nn = wn * 32 + nf * 8 + g;
            uint4 v = sB[(ks * 64 + nn) * 4 + t];
            unsigned bh[2] = {v.x, v.y}, bl[2] = {v.z, v.w};
            mma16816(acc[nf], ah, bh);
            mma16816(acc[nf], ah, bl);
        }
    }

    int r0 = row0 + wm * 16 + g, r1 = r0 + 8;
    float d0 = (r0 < n) ? g_dis[r0] : 0.f;
    float d1 = (r1 < n) ? g_dis[r1] : 0.f;
#pragma unroll
    for (int nf = 0; nf < 4; nf++) {
        int col = wn * 32 + nf * 8 + t * 2;
        if (r0 < n)
            *(__half2*)(g_h + (size_t)r0 * 64 + col) =
                __floats2half2_rn(acc[nf][0] * d0, acc[nf][1] * d0);
        if (r1 < n)
            *(__half2*)(g_h + (size_t)r1 * 64 + col) =
                __floats2half2_rn(acc[nf][2] * d1, acc[nf][3] * d1);
    }
}

// ---------------- aggregation: warp per dst node (R10 proven body) ----------
template <bool FC>
__global__ void __launch_bounds__(256) k_agg(const float* __restrict__ bias,
                                             const float* __restrict__ Wfc,
                                             const float* __restrict__ bfc,
                                             float* __restrict__ out, int n) {
    int w = (blockIdx.x * 256 + threadIdx.x) >> 5;
    int lane = threadIdx.x & 31;
    if (w >= n) return;

    int start = w ? (__ldg(&g_rptr[w - 1]) + __ldg(&g_bsum[(w - 1) >> 10])) : 0;
    int end = __ldg(&g_rptr[w]) + __ldg(&g_bsum[w >> 10]);

    const __half2* __restrict__ H2 = (const __half2*)g_h;
    float2 acc = __half22float2(H2[(size_t)w * 32 + lane]);   // self loop

    int e = start;
    for (; e + 4 <= end; e += 4) {
        int s0 = __ldg(&g_col[e]), s1 = __ldg(&g_col[e + 1]);
        int s2 = __ldg(&g_col[e + 2]), s3 = __ldg(&g_col[e + 3]);
        float2 v0 = __half22float2(H2[(size_t)s0 * 32 + lane]);
        float2 v1 = __half22float2(H2[(size_t)s1 * 32 + lane]);
        float2 v2 = __half22float2(H2[(size_t)s2 * 32 + lane]);
        float2 v3 = __half22float2(H2[(size_t)s3 * 32 + lane]);
        acc.x += (v0.x + v1.x) + (v2.x + v3.x);
        acc.y += (v0.y + v1.y) + (v2.y + v3.y);
    }
    for (; e < end; e++) {
        float2 v = __half22float2(H2[(size_t)__ldg(&g_col[e]) * 32 + lane]);
        acc.x += v.x;
        acc.y += v.y;
    }

    float d = g_dis[w];
    float2 b = ((const float2*)bias)[lane];
    float ox = fmaxf(fmaf(acc.x, d, b.x), 0.f);
    float oy = fmaxf(fmaf(acc.y, d, b.y), 0.f);

    if (!FC) {
        ((__half2*)g_a)[(size_t)w * 32 + lane] = __floats2half2_rn(ox, oy);
    } else {
        const float4* Wf = (const float4*)Wfc;   // [64][4]
        float4 w0 = Wf[2 * lane], w1 = Wf[2 * lane + 1];
        float4 y;
        y.x = ox * w0.x + oy * w1.x;
        y.y = ox * w0.y + oy * w1.y;
        y.z = ox * w0.z + oy * w1.z;
        y.w = ox * w0.w + oy * w1.w;
#pragma unroll
        for (int o = 16; o; o >>= 1) {
            y.x += __shfl_xor_sync(0xffffffffu, y.x, o);
            y.y += __shfl_xor_sync(0xffffffffu, y.y, o);
            y.z += __shfl_xor_sync(0xffffffffu, y.z, o);
            y.w += __shfl_xor_sync(0xffffffffu, y.w, o);
        }
        if (lane == 0) {
            float4 bf = *(const float4*)bfc;
            ((float4*)out)[w] = make_float4(y.x + bf.x, y.y + bf.y, y.z + bf.z, y.w + bf.w);
        }
    }
}

// ---------------- launch ----------------------------------------------------

extern "C" void kernel_launch(void* const* d_in, const int* in_sizes, int n_in,
                              void* d_out, int out_size) {
    const float* x   = (const float*)d_in[0];
    const int*   ei  = (const int*)d_in[1];
    const float* W1  = (const float*)d_in[2];
    const float* b1  = (const float*)d_in[3];
    const float* W2  = (const float*)d_in[4];
    const float* b2  = (const float*)d_in[5];
    const float* Wfc = (const float*)d_in[6];
    const float* bfc = (const float*)d_in[7];

    int n = in_sizes[0] / 128;
    int E = in_sizes[1] / 2;
    if (n > NMAX) n = NMAX;
    if (E > ECAP) E = ECAP;
    const int* src = ei;
    const int* dst = ei + E;
    int nb = (n + 1023) / 1024;
    int e4b = (E / 4 + 256) / 256;
    int gb = (n + 63) / 64;

    const int SMF = 4 * 64 * (128 + 8) * 2;                      // 69632
    const int SM2 = (64 / 16) * 64 * 4 * 16 + 64 * (64 + 8) * 2; // 25600
    cudaFuncSetAttribute(k_gemm1_fill,
                         cudaFuncAttributeMaxDynamicSharedMemorySize, SMF);
    cudaFuncSetAttribute(k_gemm2_mma,
                         cudaFuncAttributeMaxDynamicSharedMemorySize, SM2);

    k_hist<<<e4b, 256>>>(dst, E);
    k_scan1<<<nb, 1024>>>(n);
    k_scan2<<<1, 1024>>>(nb);

    // fused: gemm1 + CSR fill, roles interleaved across the grid
    k_gemm1_fill<<<gb + e4b, 256, SMF>>>(x, W1, n, gb, src, dst, E, e4b);

    k_agg<false><<<(n + 7) / 8, 256>>>(b1, nullptr, nullptr, nullptr, n);
    k_gemm2_mma<<<gb, 256, SM2>>>(W2, n);
    k_agg<true><<<(n + 7) / 8, 256>>>(b2, Wfc, bfc, (float*)d_out, n);
}

// round 16
// speedup vs baseline: 1.1168x; 1.0851x over previous
#include <cuda_runtime.h>
#include <cuda_fp16.h>

// ---------------- scratch (device globals; no allocation allowed) ----------
#define NMAX  100032
#define ECAP  1664000

__device__ __half g_h [NMAX * 64];   // layer-1 activations, fp16 (gather src, READ-ONLY in fused kernel)
__device__ __half g_h2[NMAX * 64];   // layer-2 gemm output (WRITE-ONLY in fused kernel)
__device__ float  g_dis[NMAX];
__device__ int    g_cnt[NMAX];       // zero at entry (module init / scan1 re-zero)
__device__ int    g_rptr[NMAX];      // after fill: block-local inclusive prefix
__device__ int    g_col[ECAP];
__device__ int    g_bsum[128];       // exclusive scan of block totals (carry)

// ---------------- preprocessing kernels ------------------------------------

__global__ void k_hist(const int* __restrict__ dst, int E) {
    int e = (blockIdx.x * 256 + threadIdx.x) * 4;
    if (e + 4 <= E) {
        int4 d = *(const int4*)(dst + e);
        atomicAdd(&g_cnt[d.x], 1);
        atomicAdd(&g_cnt[d.y], 1);
        atomicAdd(&g_cnt[d.z], 1);
        atomicAdd(&g_cnt[d.w], 1);
    } else {
        for (; e < E; e++) atomicAdd(&g_cnt[dst[e]], 1);
    }
}

// block-wide exclusive scan helper (blockDim.x == 1024)
__device__ __forceinline__ int blockscan_excl(int v, int* total) {
    __shared__ int ws[32];
    int lane = threadIdx.x & 31, wid = threadIdx.x >> 5;
    int s = v;
#pragma unroll
    for (int o = 1; o < 32; o <<= 1) {
        int t = __shfl_up_sync(0xffffffffu, s, o);
        if (lane >= o) s += t;
    }
    if (lane == 31) ws[wid] = s;
    __syncthreads();
    if (wid == 0) {
        int u = ws[lane];
#pragma unroll
        for (int o = 1; o < 32; o <<= 1) {
            int t = __shfl_up_sync(0xffffffffu, u, o);
            if (lane >= o) u += t;
        }
        ws[lane] = u;
    }
    __syncthreads();
    int incl = s + (wid ? ws[wid - 1] : 0);
    if (total) *total = ws[31];
    return incl - v;
}

// per-block exclusive scan of cnt -> rptr (local), block totals -> bsum,
// fused with dis = rsqrt(deg+1). Re-zeroes g_cnt so the next graph replay's
// hist starts from zero (module load zero-inits for call #1; proven R13/R14).
__global__ void k_scan1(int n) {
    int i = blockIdx.x * 1024 + threadIdx.x;
    int v = (i < n) ? g_cnt[i] : 0;
    int tot;
    int ex = blockscan_excl(v, &tot);
    if (i < n) {
        g_rptr[i] = ex;
        g_dis[i] = rsqrtf((float)(v + 1));   // +1 self loop; always > 0
        g_cnt[i] = 0;
    }
    if (threadIdx.x == 0) g_bsum[blockIdx.x] = tot;
}

// exclusive scan of block sums (single block)
__global__ void k_scan2(int nb) {
    int i = threadIdx.x;
    int v = (i < nb) ? g_bsum[i] : 0;   // reads complete before writes (barrier in scan)
    int ex = blockscan_excl(v, nullptr);
    if (i < nb) g_bsum[i] = ex;
}

// ---------------- mma.sync helpers ------------------------------------------
__device__ __forceinline__ void mma16816(float acc[4], const unsigned a[4],
                                         const unsigned b[2]) {
    asm volatile(
        "mma.sync.aligned.m16n8k16.row.col.f32.f16.f16.f32 "
        "{%0,%1,%2,%3}, {%4,%5,%6,%7}, {%8,%9}, {%0,%1,%2,%3};\n"
        : "+f"(acc[0]), "+f"(acc[1]), "+f"(acc[2]), "+f"(acc[3])
        : "r"(a[0]), "r"(a[1]), "r"(a[2]), "r"(a[3]), "r"(b[0]), "r"(b[1]));
}

__device__ __forceinline__ unsigned pack_hi(float2 f, unsigned& lo) {
    __half hx = __float2half_rn(f.x), hy = __float2half_rn(f.y);
    __half2 l2 = __halves2half2(__float2half_rn(f.x - __half2float(hx)),
                                __float2half_rn(f.y - __half2float(hy)));
    lo = *(unsigned*)&l2;
    __half2 h2 = __halves2half2(hx, hy);
    return *(unsigned*)&h2;
}

// Stage W[K][64] (row-major fp32) into per-thread B-fragment records:
//   sB[(ks*64 + nn)*4 + t] = {bh0, bh1, bl0, bl1}; decomposition of i must
//   match consumer index: t = i&3, nn = (i>>2)&63, ks = i>>8.
template <int K>
__device__ __forceinline__ void stage_B(uint4* sB, const float* __restrict__ W,
                                        int tid) {
    constexpr int ENT = (K / 16) * 64 * 4;
    for (int i = tid; i < ENT; i += 256) {
        int t = i & 3;
        int nn = (i >> 2) & 63;
        int ks = i >> 8;
        int k0 = ks * 16 + t * 2;
        float w0 = W[k0 * 64 + nn],       w1 = W[(k0 + 1) * 64 + nn];
        float w2 = W[(k0 + 8) * 64 + nn], w3 = W[(k0 + 9) * 64 + nn];
        unsigned l01, l23;
        uint4 v;
        v.x = pack_hi(make_float2(w0, w1), l01);
        v.y = pack_hi(make_float2(w2, w3), l23);
        v.z = l01;
        v.w = l23;
        sB[i] = v;
    }
}

// ---------------- FUSED: gemm1 + CSR fill, role-interleaved (R10 exact) -----
__global__ void __launch_bounds__(256) k_gemm1_fill(
        const float* __restrict__ Ain, const float* __restrict__ W, int n, int gb,
        const int* __restrict__ src, const int* __restrict__ dst, int E, int e4b) {
    constexpr int K = 128;
    extern __shared__ __align__(16) uint4 sB[];   // [(K/16)*64*4] = 32 KB

    int mn = (gb < e4b) ? gb : e4b;
    int m2 = 2 * mn;
    bool isFill;
    int id;
    if ((int)blockIdx.x < m2) {
        isFill = (blockIdx.x & 1) == 0;
        id = blockIdx.x >> 1;
    } else {
        int rem = blockIdx.x - m2;
        isFill = (e4b > gb);
        id = mn + rem;
    }

    if (isFill) {
        // ---------------- fill body ----------------
        int e = (id * 256 + threadIdx.x) * 4;
        if (e + 4 <= E) {
            int4 d = *(const int4*)(dst + e);
            int4 s = *(const int4*)(src + e);
            g_col[atomicAdd(&g_rptr[d.x], 1) + g_bsum[d.x >> 10]] = s.x;
            g_col[atomicAdd(&g_rptr[d.y], 1) + g_bsum[d.y >> 10]] = s.y;
            g_col[atomicAdd(&g_rptr[d.z], 1) + g_bsum[d.z >> 10]] = s.z;
            g_col[atomicAdd(&g_rptr[d.w], 1) + g_bsum[d.w >> 10]] = s.w;
        } else {
            for (; e < E; e++) {
                int d = dst[e];
                g_col[atomicAdd(&g_rptr[d], 1) + g_bsum[d >> 10]] = src[e];
            }
        }
        return;
    }

    // ---------------- gemm1 body (R10 exact: A direct from global) ----------
    int tid = threadIdx.x;
    int wid = tid >> 5, lane = tid & 31;
    int wm = wid & 3, wn = wid >> 2;
    int row0 = id * 64;

    stage_B<K>(sB, W, tid);
    __syncthreads();

    float acc[4][4];
#pragma unroll
    for (int f = 0; f < 4; f++)
#pragma unroll
        for (int j = 0; j < 4; j++) acc[f][j] = 0.f;

    int g = lane >> 2, t = lane & 3;
    int r0 = row0 + wm * 16 + g, r1 = r0 + 8;
    bool ok0 = r0 < n, ok1 = r1 < n;
    const float* A0 = Ain + (size_t)r0 * K;
    const float* A1 = Ain + (size_t)r1 * K;
    const float2 z2 = make_float2(0.f, 0.f);

#pragma unroll
    for (int ks = 0; ks < K / 16; ks++) {
        int kk = ks * 16 + t * 2;
        float2 f0 = ok0 ? *(const float2*)(A0 + kk) : z2;
        float2 f1 = ok1 ? *(const float2*)(A1 + kk) : z2;
        float2 f2 = ok0 ? *(const float2*)(A0 + kk + 8) : z2;
        float2 f3 = ok1 ? *(const float2*)(A1 + kk + 8) : z2;
        unsigned ah[4], al[4];
        ah[0] = pack_hi(f0, al[0]);
        ah[1] = pack_hi(f1, al[1]);
        ah[2] = pack_hi(f2, al[2]);
        ah[3] = pack_hi(f3, al[3]);
#pragma unroll
        for (int nf = 0; nf < 4; nf++) {
            int nn = wn * 32 + nf * 8 + g;
            uint4 v = sB[(ks * 64 + nn) * 4 + t];
            unsigned bh[2] = {v.x, v.y}, bl[2] = {v.z, v.w};
            mma16816(acc[nf], ah, bh);
            mma16816(acc[nf], ah, bl);
            mma16816(acc[nf], al, bh);
        }
    }

    float d0 = ok0 ? g_dis[r0] : 0.f;
    float d1 = ok1 ? g_dis[r1] : 0.f;
#pragma unroll
    for (int nf = 0; nf < 4; nf++) {
        int col = wn * 32 + nf * 8 + t * 2;
        if (ok0)
            *(__half2*)(g_h + (size_t)r0 * 64 + col) =
                __floats2half2_rn(acc[nf][0] * d0, acc[nf][1] * d0);
        if (ok1)
            *(__half2*)(g_h + (size_t)r1 * 64 + col) =
                __floats2half2_rn(acc[nf][2] * d1, acc[nf][3] * d1);
    }
}

// ---------------- FUSED: agg1 + gemm2 ---------------------------------------
// Block owns 64 nodes. Phase 1: each of 8 warps aggregates 8 nodes (identical
// arithmetic to the standalone agg: fp32 accumulate over self-loop + CSR
// neighbors from g_h, scale by dis, +bias, relu, single fp16 rounding),
// writing activation rows DIRECTLY into the smem A-tile. Phase 2 (after one
// barrier): unchanged gemm2 MMA body writes dis-scaled fp16 to g_h2.
// RACE FIX vs R15: output goes to g_h2, NOT g_h — g_h stays read-only while
// any block may still be gathering layer-1 activations from it.
__global__ void __launch_bounds__(256) k_agg1_gemm2(
        const float* __restrict__ bias, const float* __restrict__ W, int n) {
    constexpr int K = 64;
    constexpr int LD = K + 8;
    extern __shared__ __align__(16) uint4 dynu[];
    uint4* sB = dynu;                                   // [(K/16)*64*4] = 16 KB
    __half* sA = (__half*)(dynu + (K / 16) * 64 * 4);   // [64][LD] = 9216 B

    int tid = threadIdx.x;
    int wid = tid >> 5, lane = tid & 31;
    int row0 = blockIdx.x * 64;

    stage_B<K>(sB, W, tid);

    // -------- phase 1: aggregate 8 nodes per warp into sA --------
    const __half2* __restrict__ H2 = (const __half2*)g_h;
    float2 b = ((const float2*)bias)[lane];
#pragma unroll 1
    for (int j = 0; j < 8; j++) {
        int lr = wid * 8 + j;            // local row 0..63
        int w = row0 + lr;
        __half2 outv = __halves2half2(__ushort_as_half(0), __ushort_as_half(0));
        if (w < n) {
            int start = w ? (__ldg(&g_rptr[w - 1]) + __ldg(&g_bsum[(w - 1) >> 10])) : 0;
            int end = __ldg(&g_rptr[w]) + __ldg(&g_bsum[w >> 10]);

            float2 acc = __half22float2(H2[(size_t)w * 32 + lane]);   // self loop
            int e = start;
            for (; e + 4 <= end; e += 4) {
                int s0 = __ldg(&g_col[e]), s1 = __ldg(&g_col[e + 1]);
                int s2 = __ldg(&g_col[e + 2]), s3 = __ldg(&g_col[e + 3]);
                float2 v0 = __half22float2(H2[(size_t)s0 * 32 + lane]);
                float2 v1 = __half22float2(H2[(size_t)s1 * 32 + lane]);
                float2 v2 = __half22float2(H2[(size_t)s2 * 32 + lane]);
                float2 v3 = __half22float2(H2[(size_t)s3 * 32 + lane]);
                acc.x += (v0.x + v1.x) + (v2.x + v3.x);
                acc.y += (v0.y + v1.y) + (v2.y + v3.y);
            }
            for (; e < end; e++) {
                float2 v = __half22float2(H2[(size_t)__ldg(&g_col[e]) * 32 + lane]);
                acc.x += v.x;
                acc.y += v.y;
            }
            float d = g_dis[w];
            outv = __floats2half2_rn(fmaxf(fmaf(acc.x, d, b.x), 0.f),
                                     fmaxf(fmaf(acc.y, d, b.y), 0.f));
        }
        *(__half2*)(sA + lr * LD + lane * 2) = outv;
    }
    __syncthreads();

    // -------- phase 2: gemm2 MMA from smem -> g_h2 --------
    int wm = wid & 3, wn = wid >> 2;
    float acc[4][4];
#pragma unroll
    for (int f = 0; f < 4; f++)
#pragma unroll
        for (int j = 0; j < 4; j++) acc[f][j] = 0.f;

    int g = lane >> 2, t = lane & 3;

#pragma unroll
    for (int ks = 0; ks < K / 16; ks++) {
        int kk = ks * 16 + t * 2;
        int r = wm * 16 + g;
        unsigned ah[4];
        ah[0] = *(const unsigned*)(sA + r * LD + kk);
        ah[1] = *(const unsigned*)(sA + (r + 8) * LD + kk);
        ah[2] = *(const unsigned*)(sA + r * LD + kk + 8);
        ah[3] = *(const unsigned*)(sA + (r + 8) * LD + kk + 8);
#pragma unroll
        for (int nf = 0; nf < 4; nf++) {
            int nn = wn * 32 + nf * 8 + g;
            uint4 v = sB[(ks * 64 + nn) * 4 + t];
            unsigned bh[2] = {v.x, v.y}, bl[2] = {v.z, v.w};
            mma16816(acc[nf], ah, bh);
            mma16816(acc[nf], ah, bl);
        }
    }

    int r0 = row0 + wm * 16 + g, r1 = r0 + 8;
    float d0 = (r0 < n) ? g_dis[r0] : 0.f;
    float d1 = (r1 < n) ? g_dis[r1] : 0.f;
#pragma unroll
    for (int nf = 0; nf < 4; nf++) {
        int col = wn * 32 + nf * 8 + t * 2;
        if (r0 < n)
            *(__half2*)(g_h2 + (size_t)r0 * 64 + col) =
                __floats2half2_rn(acc[nf][0] * d0, acc[nf][1] * d0);
        if (r1 < n)
            *(__half2*)(g_h2 + (size_t)r1 * 64 + col) =
                __floats2half2_rn(acc[nf][2] * d1, acc[nf][3] * d1);
    }
}

// ---------------- agg2: warp per dst node + FC epilogue (gathers g_h2) ------
__global__ void __launch_bounds__(256) k_agg2(const float* __restrict__ bias,
                                              const float* __restrict__ Wfc,
                                              const float* __restrict__ bfc,
                                              float* __restrict__ out, int n) {
    int w = (blockIdx.x * 256 + threadIdx.x) >> 5;
    int lane = threadIdx.x & 31;
    if (w >= n) return;

    int start = w ? (__ldg(&g_rptr[w - 1]) + __ldg(&g_bsum[(w - 1) >> 10])) : 0;
    int end = __ldg(&g_rptr[w]) + __ldg(&g_bsum[w >> 10]);

    const __half2* __restrict__ H2 = (const __half2*)g_h2;
    float2 acc = __half22float2(H2[(size_t)w * 32 + lane]);   // self loop

    int e = start;
    for (; e + 4 <= end; e += 4) {
        int s0 = __ldg(&g_col[e]), s1 = __ldg(&g_col[e + 1]);
        int s2 = __ldg(&g_col[e + 2]), s3 = __ldg(&g_col[e + 3]);
        float2 v0 = __half22float2(H2[(size_t)s0 * 32 + lane]);
        float2 v1 = __half22float2(H2[(size_t)s1 * 32 + lane]);
        float2 v2 = __half22float2(H2[(size_t)s2 * 32 + lane]);
        float2 v3 = __half22float2(H2[(size_t)s3 * 32 + lane]);
        acc.x += (v0.x + v1.x) + (v2.x + v3.x);
        acc.y += (v0.y + v1.y) + (v2.y + v3.y);
    }
    for (; e < end; e++) {
        float2 v = __half22float2(H2[(size_t)__ldg(&g_col[e]) * 32 + lane]);
        acc.x += v.x;
        acc.y += v.y;
    }

    float d = g_dis[w];
    float2 b = ((const float2*)bias)[lane];
    float ox = fmaxf(fmaf(acc.x, d, b.x), 0.f);
    float oy = fmaxf(fmaf(acc.y, d, b.y), 0.f);

    const float4* Wf = (const float4*)Wfc;   // [64][4]
    float4 w0 = Wf[2 * lane], w1 = Wf[2 * lane + 1];
    float4 y;
    y.x = ox * w0.x + oy * w1.x;
    y.y = ox * w0.y + oy * w1.y;
    y.z = ox * w0.z + oy * w1.z;
    y.w = ox * w0.w + oy * w1.w;
#pragma unroll
    for (int o = 16; o; o >>= 1) {
        y.x += __shfl_xor_sync(0xffffffffu, y.x, o);
        y.y += __shfl_xor_sync(0xffffffffu, y.y, o);
        y.z += __shfl_xor_sync(0xffffffffu, y.z, o);
        y.w += __shfl_xor_sync(0xffffffffu, y.w, o);
    }
    if (lane == 0) {
        float4 bf = *(const float4*)bfc;
        ((float4*)out)[w] = make_float4(y.x + bf.x, y.y + bf.y, y.z + bf.z, y.w + bf.w);
    }
}

// ---------------- launch ----------------------------------------------------

extern "C" void kernel_launch(void* const* d_in, const int* in_sizes, int n_in,
                              void* d_out, int out_size) {
    const float* x   = (const float*)d_in[0];
    const int*   ei  = (const int*)d_in[1];
    const float* W1  = (const float*)d_in[2];
    const float* b1  = (const float*)d_in[3];
    const float* W2  = (const float*)d_in[4];
    const float* b2  = (const float*)d_in[5];
    const float* Wfc = (const float*)d_in[6];
    const float* bfc = (const float*)d_in[7];

    int n = in_sizes[0] / 128;
    int E = in_sizes[1] / 2;
    if (n > NMAX) n = NMAX;
    if (E > ECAP) E = ECAP;
    const int* src = ei;
    const int* dst = ei + E;
    int nb = (n + 1023) / 1024;
    int e4b = (E / 4 + 256) / 256;
    int gb = (n + 63) / 64;

    const int SMF = (128 / 16) * 64 * 4 * 16;                    // 32768
    const int SM2 = (64 / 16) * 64 * 4 * 16 + 64 * (64 + 8) * 2; // 25600
    cudaFuncSetAttribute(k_gemm1_fill,
                         cudaFuncAttributeMaxDynamicSharedMemorySize, SMF);
    cudaFuncSetAttribute(k_agg1_gemm2,
                         cudaFuncAttributeMaxDynamicSharedMemorySize, SM2);

    k_hist<<<e4b, 256>>>(dst, E);
    k_scan1<<<nb, 1024>>>(n);
    k_scan2<<<1, 1024>>>(nb);

    // fused: gemm1 + CSR fill, roles interleaved across the grid
    k_gemm1_fill<<<gb + e4b, 256, SMF>>>(x, W1, n, gb, src, dst, E, e4b);

    // fused: agg1 -> smem A-tile -> gemm2 -> g_h2 (g_h stays read-only)
    k_agg1_gemm2<<<gb, 256, SM2>>>(b1, W2, n);

    k_agg2<<<(n + 7) / 8, 256>>>(b2, Wfc, bfc, (float*)d_out, n);
}

// round 17
// speedup vs baseline: 1.1691x; 1.0469x over previous
#include <cuda_runtime.h>
#include <cuda_fp16.h>

// ---------------- scratch (device globals; no allocation allowed) ----------
#define NMAX  100032
#define ECAP  1664000

__device__ __half g_h [NMAX * 64];   // layer-1 activations, fp16 (gather src)
__device__ __half g_a [NMAX * 64];   // post-agg1 activations, fp16
__device__ float  g_dis[NMAX];
__device__ int    g_cnt[NMAX];       // zero at entry (module init / scan1 re-zero)
__device__ int    g_rptr[NMAX];      // after fill: block-local inclusive prefix
__device__ int    g_col[ECAP];
__device__ int    g_bsum[128];       // exclusive scan of block totals (carry)

// ---------------- preprocessing kernels ------------------------------------

__global__ void k_hist(const int* __restrict__ dst, int E) {
    int e = (blockIdx.x * 256 + threadIdx.x) * 4;
    if (e + 4 <= E) {
        int4 d = *(const int4*)(dst + e);
        atomicAdd(&g_cnt[d.x], 1);
        atomicAdd(&g_cnt[d.y], 1);
        atomicAdd(&g_cnt[d.z], 1);
        atomicAdd(&g_cnt[d.w], 1);
    } else {
        for (; e < E; e++) atomicAdd(&g_cnt[dst[e]], 1);
    }
}

// block-wide exclusive scan helper (blockDim.x == 1024)
__device__ __forceinline__ int blockscan_excl(int v, int* total) {
    __shared__ int ws[32];
    int lane = threadIdx.x & 31, wid = threadIdx.x >> 5;
    int s = v;
#pragma unroll
    for (int o = 1; o < 32; o <<= 1) {
        int t = __shfl_up_sync(0xffffffffu, s, o);
        if (lane >= o) s += t;
    }
    if (lane == 31) ws[wid] = s;
    __syncthreads();
    if (wid == 0) {
        int u = ws[lane];
#pragma unroll
        for (int o = 1; o < 32; o <<= 1) {
            int t = __shfl_up_sync(0xffffffffu, u, o);
            if (lane >= o) u += t;
        }
        ws[lane] = u;
    }
    __syncthreads();
    int incl = s + (wid ? ws[wid - 1] : 0);
    if (total) *total = ws[31];
    return incl - v;
}

// per-block exclusive scan of cnt -> rptr (local), block totals -> bsum,
// fused with dis = rsqrt(deg+1). Re-zeroes g_cnt so the next graph replay's
// hist starts from zero (module load zero-inits for call #1; proven R13-R16).
__global__ void k_scan1(int n) {
    int i = blockIdx.x * 1024 + threadIdx.x;
    int v = (i < n) ? g_cnt[i] : 0;
    int tot;
    int ex = blockscan_excl(v, &tot);
    if (i < n) {
        g_rptr[i] = ex;
        g_dis[i] = rsqrtf((float)(v + 1));   // +1 self loop; always > 0
        g_cnt[i] = 0;
    }
    if (threadIdx.x == 0) g_bsum[blockIdx.x] = tot;
}

// exclusive scan of block sums (single block)
__global__ void k_scan2(int nb) {
    int i = threadIdx.x;
    int v = (i < nb) ? g_bsum[i] : 0;   // reads complete before writes (barrier in scan)
    int ex = blockscan_excl(v, nullptr);
    if (i < nb) g_bsum[i] = ex;
}

// ---------------- mma.sync helpers ------------------------------------------
__device__ __forceinline__ void mma16816(float acc[4], const unsigned a[4],
                                         const unsigned b[2]) {
    asm volatile(
        "mma.sync.aligned.m16n8k16.row.col.f32.f16.f16.f32 "
        "{%0,%1,%2,%3}, {%4,%5,%6,%7}, {%8,%9}, {%0,%1,%2,%3};\n"
        : "+f"(acc[0]), "+f"(acc[1]), "+f"(acc[2]), "+f"(acc[3])
        : "r"(a[0]), "r"(a[1]), "r"(a[2]), "r"(a[3]), "r"(b[0]), "r"(b[1]));
}

__device__ __forceinline__ unsigned pack_hi(float2 f, unsigned& lo) {
    __half hx = __float2half_rn(f.x), hy = __float2half_rn(f.y);
    __half2 l2 = __halves2half2(__float2half_rn(f.x - __half2float(hx)),
                                __float2half_rn(f.y - __half2float(hy)));
    lo = *(unsigned*)&l2;
    __half2 h2 = __halves2half2(hx, hy);
    return *(unsigned*)&h2;
}

// Stage W[K][64] (row-major fp32) into per-thread B-fragment records:
//   sB[(ks*64 + nn)*4 + t] = {bh0, bh1, bl0, bl1}; decomposition of i must
//   match consumer index: t = i&3, nn = (i>>2)&63, ks = i>>8.
template <int K>
__device__ __forceinline__ void stage_B(uint4* sB, const float* __restrict__ W,
                                        int tid) {
    constexpr int ENT = (K / 16) * 64 * 4;
    for (int i = tid; i < ENT; i += 256) {
        int t = i & 3;
        int nn = (i >> 2) & 63;
        int ks = i >> 8;
        int k0 = ks * 16 + t * 2;
        float w0 = W[k0 * 64 + nn],       w1 = W[(k0 + 1) * 64 + nn];
        float w2 = W[(k0 + 8) * 64 + nn], w3 = W[(k0 + 9) * 64 + nn];
        unsigned l01, l23;
        uint4 v;
        v.x = pack_hi(make_float2(w0, w1), l01);
        v.y = pack_hi(make_float2(w2, w3), l23);
        v.z = l01;
        v.w = l23;
        sB[i] = v;
    }
}

// ---------------- FUSED: gemm1 + CSR fill, role-interleaved (R10 exact) -----
__global__ void __launch_bounds__(256) k_gemm1_fill(
        const float* __restrict__ Ain, const float* __restrict__ W, int n, int gb,
        const int* __restrict__ src, const int* __restrict__ dst, int E, int e4b) {
    constexpr int K = 128;
    extern __shared__ __align__(16) uint4 sB[];   // [(K/16)*64*4] = 32 KB

    int mn = (gb < e4b) ? gb : e4b;
    int m2 = 2 * mn;
    bool isFill;
    int id;
    if ((int)blockIdx.x < m2) {
        isFill = (blockIdx.x & 1) == 0;
        id = blockIdx.x >> 1;
    } else {
        int rem = blockIdx.x - m2;
        isFill = (e4b > gb);
        id = mn + rem;
    }

    if (isFill) {
        // ---------------- fill body ----------------
        int e = (id * 256 + threadIdx.x) * 4;
        if (e + 4 <= E) {
            int4 d = *(const int4*)(dst + e);
            int4 s = *(const int4*)(src + e);
            g_col[atomicAdd(&g_rptr[d.x], 1) + g_bsum[d.x >> 10]] = s.x;
            g_col[atomicAdd(&g_rptr[d.y], 1) + g_bsum[d.y >> 10]] = s.y;
            g_col[atomicAdd(&g_rptr[d.z], 1) + g_bsum[d.z >> 10]] = s.z;
            g_col[atomicAdd(&g_rptr[d.w], 1) + g_bsum[d.w >> 10]] = s.w;
        } else {
            for (; e < E; e++) {
                int d = dst[e];
                g_col[atomicAdd(&g_rptr[d], 1) + g_bsum[d >> 10]] = src[e];
            }
        }
        return;
    }

    // ---------------- gemm1 body (R10 exact: A direct from global) ----------
    int tid = threadIdx.x;
    int wid = tid >> 5, lane = tid & 31;
    int wm = wid & 3, wn = wid >> 2;
    int row0 = id * 64;

    stage_B<K>(sB, W, tid);
    __syncthreads();

    float acc[4][4];
#pragma unroll
    for (int f = 0; f < 4; f++)
#pragma unroll
        for (int j = 0; j < 4; j++) acc[f][j] = 0.f;

    int g = lane >> 2, t = lane & 3;
    int r0 = row0 + wm * 16 + g, r1 = r0 + 8;
    bool ok0 = r0 < n, ok1 = r1 < n;
    const float* A0 = Ain + (size_t)r0 * K;
    const float* A1 = Ain + (size_t)r1 * K;
    const float2 z2 = make_float2(0.f, 0.f);

#pragma unroll
    for (int ks = 0; ks < K / 16; ks++) {
        int kk = ks * 16 + t * 2;
        float2 f0 = ok0 ? *(const float2*)(A0 + kk) : z2;
        float2 f1 = ok1 ? *(const float2*)(A1 + kk) : z2;
        float2 f2 = ok0 ? *(const float2*)(A0 + kk + 8) : z2;
        float2 f3 = ok1 ? *(const float2*)(A1 + kk + 8) : z2;
        unsigned ah[4], al[4];
        ah[0] = pack_hi(f0, al[0]);
        ah[1] = pack_hi(f1, al[1]);
        ah[2] = pack_hi(f2, al[2]);
        ah[3] = pack_hi(f3, al[3]);
#pragma unroll
        for (int nf = 0; nf < 4; nf++) {
            int nn = wn * 32 + nf * 8 + g;
            uint4 v = sB[(ks * 64 + nn) * 4 + t];
            unsigned bh[2] = {v.x, v.y}, bl[2] = {v.z, v.w};
            mma16816(acc[nf], ah, bh);
            mma16816(acc[nf], ah, bl);
            mma16816(acc[nf], al, bh);
        }
    }

    float d0 = ok0 ? g_dis[r0] : 0.f;
    float d1 = ok1 ? g_dis[r1] : 0.f;
#pragma unroll
    for (int nf = 0; nf < 4; nf++) {
        int col = wn * 32 + nf * 8 + t * 2;
        if (ok0)
            *(__half2*)(g_h + (size_t)r0 * 64 + col) =
                __floats2half2_rn(acc[nf][0] * d0, acc[nf][1] * d0);
        if (ok1)
            *(__half2*)(g_h + (size_t)r1 * 64 + col) =
                __floats2half2_rn(acc[nf][2] * d1, acc[nf][3] * d1);
    }
}

// ---------------- GEMM2 via mma.sync (R10 exact) ----------------------------
// H[n,64] = (g_a[n,64] @ W2) * dis[row] -> fp16 g_h ; A exact fp16 from smem.
__global__ void __launch_bounds__(256) k_gemm2_mma(const float* __restrict__ W, int n) {
    constexpr int K = 64;
    constexpr int LD = K + 8;
    extern __shared__ __align__(16) uint4 dynu[];
    uint4* sB = dynu;                                   // [(K/16)*64*4] = 16 KB
    __half* sAh = (__half*)(dynu + (K / 16) * 64 * 4);  // [64][LD]

    int tid = threadIdx.x;
    int wid = tid >> 5, lane = tid & 31;
    int wm = wid & 3, wn = wid >> 2;
    int row0 = blockIdx.x * 64;

    stage_B<K>(sB, W, tid);
    for (int i = tid; i < 64 * (K / 8); i += 256) {
        int row = i / (K / 8), c8 = i % (K / 8);
        uint4 v = *(const uint4*)(g_a + (size_t)(row0 + row) * K + c8 * 8);
        *(uint4*)(sAh + row * LD + c8 * 8) = v;
    }
    __syncthreads();

    float acc[4][4];
#pragma unroll
    for (int f = 0; f < 4; f++)
#pragma unroll
        for (int j = 0; j < 4; j++) acc[f][j] = 0.f;

    int g = lane >> 2, t = lane & 3;

#pragma unroll
    for (int ks = 0; ks < K / 16; ks++) {
        int kk = ks * 16 + t * 2;
        int r = wm * 16 + g;
        unsigned ah[4];
        ah[0] = *(const unsigned*)(sAh + r * LD + kk);
        ah[1] = *(const unsigned*)(sAh + (r + 8) * LD + kk);
        ah[2] = *(const unsigned*)(sAh + r * LD + kk + 8);
        ah[3] = *(const unsigned*)(sAh + (r + 8) * LD + kk + 8);
#pragma unroll
        for (int nf = 0; nf < 4; nf++) {
            int nn = wn * 32 + nf * 8 + g;
            uint4 v = sB[(ks * 64 + nn) * 4 + t];
            unsigned bh[2] = {v.x, v.y}, bl[2] = {v.z, v.w};
            mma16816(acc[nf], ah, bh);
            mma16816(acc[nf], ah, bl);
        }
    }

    int r0 = row0 + wm * 16 + g, r1 = r0 + 8;
    float d0 = (r0 < n) ? g_dis[r0] : 0.f;
    float d1 = (r1 < n) ? g_dis[r1] : 0.f;
#pragma unroll
    for (int nf = 0; nf < 4; nf++) {
        int col = wn * 32 + nf * 8 + t * 2;
        if (r0 < n)
            *(__half2*)(g_h + (size_t)r0 * 64 + col) =
                __floats2half2_rn(acc[nf][0] * d0, acc[nf][1] * d0);
        if (r1 < n)
            *(__half2*)(g_h + (size_t)r1 * 64 + col) =
                __floats2half2_rn(acc[nf][2] * d1, acc[nf][3] * d1);
    }
}

// ---------------- aggregation: warp per dst node (R10 exact) ----------------
template <bool FC>
__global__ void __launch_bounds__(256) k_agg(const float* __restrict__ bias,
                                             const float* __restrict__ Wfc,
                                             const float* __restrict__ bfc,
                                             float* __restrict__ out, int n) {
    int w = (blockIdx.x * 256 + threadIdx.x) >> 5;
    int lane = threadIdx.x & 31;
    if (w >= n) return;

    int start = w ? (__ldg(&g_rptr[w - 1]) + __ldg(&g_bsum[(w - 1) >> 10])) : 0;
    int end = __ldg(&g_rptr[w]) + __ldg(&g_bsum[w >> 10]);

    const __half2* __restrict__ H2 = (const __half2*)g_h;
    float2 acc = __half22float2(H2[(size_t)w * 32 + lane]);   // self loop

    int e = start;
    for (; e + 4 <= end; e += 4) {
        int s0 = __ldg(&g_col[e]), s1 = __ldg(&g_col[e + 1]);
        int s2 = __ldg(&g_col[e + 2]), s3 = __ldg(&g_col[e + 3]);
        float2 v0 = __half22float2(H2[(size_t)s0 * 32 + lane]);
        float2 v1 = __half22float2(H2[(size_t)s1 * 32 + lane]);
        float2 v2 = __half22float2(H2[(size_t)s2 * 32 + lane]);
        float2 v3 = __half22float2(H2[(size_t)s3 * 32 + lane]);
        acc.x += (v0.x + v1.x) + (v2.x + v3.x);
        acc.y += (v0.y + v1.y) + (v2.y + v3.y);
    }
    for (; e < end; e++) {
        float2 v = __half22float2(H2[(size_t)__ldg(&g_col[e]) * 32 + lane]);
        acc.x += v.x;
        acc.y += v.y;
    }

    float d = g_dis[w];
    float2 b = ((const float2*)bias)[lane];
    float ox = fmaxf(fmaf(acc.x, d, b.x), 0.f);
    float oy = fmaxf(fmaf(acc.y, d, b.y), 0.f);

    if (!FC) {
        ((__half2*)g_a)[(size_t)w * 32 + lane] = __floats2half2_rn(ox, oy);
    } else {
        const float4* Wf = (const float4*)Wfc;   // [64][4]
        float4 w0 = Wf[2 * lane], w1 = Wf[2 * lane + 1];
        float4 y;
        y.x = ox * w0.x + oy * w1.x;
        y.y = ox * w0.y + oy * w1.y;
        y.z = ox * w0.z + oy * w1.z;
        y.w = ox * w0.w + oy * w1.w;
#pragma unroll
        for (int o = 16; o; o >>= 1) {
            y.x += __shfl_xor_sync(0xffffffffu, y.x, o);
            y.y += __shfl_xor_sync(0xffffffffu, y.y, o);
            y.z += __shfl_xor_sync(0xffffffffu, y.z, o);
            y.w += __shfl_xor_sync(0xffffffffu, y.w, o);
        }
        if (lane == 0) {
            float4 bf = *(const float4*)bfc;
            ((float4*)out)[w] = make_float4(y.x + bf.x, y.y + bf.y, y.z + bf.z, y.w + bf.w);
        }
    }
}

// ---------------- launch ----------------------------------------------------

extern "C" void kernel_launch(void* const* d_in, const int* in_sizes, int n_in,
                              void* d_out, int out_size) {
    const float* x   = (const float*)d_in[0];
    const int*   ei  = (const int*)d_in[1];
    const float* W1  = (const float*)d_in[2];
    const float* b1  = (const float*)d_in[3];
    const float* W2  = (const float*)d_in[4];
    const float* b2  = (const float*)d_in[5];
    const float* Wfc = (const float*)d_in[6];
    const float* bfc = (const float*)d_in[7];

    int n = in_sizes[0] / 128;
    int E = in_sizes[1] / 2;
    if (n > NMAX) n = NMAX;
    if (E > ECAP) E = ECAP;
    const int* src = ei;
    const int* dst = ei + E;
    int nb = (n + 1023) / 1024;
    int e4b = (E / 4 + 256) / 256;
    int gb = (n + 63) / 64;

    const int SMF = (128 / 16) * 64 * 4 * 16;                    // 32768
    const int SM2 = (64 / 16) * 64 * 4 * 16 + 64 * (64 + 8) * 2; // 25600
    cudaFuncSetAttribute(k_gemm1_fill,
                         cudaFuncAttributeMaxDynamicSharedMemorySize, SMF);
    cudaFuncSetAttribute(k_gemm2_mma,
                         cudaFuncAttributeMaxDynamicSharedMemorySize, SM2);

    k_hist<<<e4b, 256>>>(dst, E);
    k_scan1<<<nb, 1024>>>(n);
    k_scan2<<<1, 1024>>>(nb);

    // fused: gemm1 + CSR fill, roles interleaved across the grid
    k_gemm1_fill<<<gb + e4b, 256, SMF>>>(x, W1, n, gb, src, dst, E, e4b);

    k_agg<false><<<(n + 7) / 8, 256>>>(b1, nullptr, nullptr, nullptr, n);
    k_gemm2_mma<<<gb, 256, SM2>>>(W2, n);
    k_agg<true><<<(n + 7) / 8, 256>>>(b2, Wfc, bfc, (float*)d_out, n);
}